// round 2
// baseline (speedup 1.0000x reference)
#include <cuda_runtime.h>
#include <math_constants.h>

#define NB      256
#define LH      150
#define LQ      10
#define KITER   40
#define WWID    64
#define HW      4096
#define VW      66            // 64 + 2 halo
#define VSZ     (VW*VW)       // 4356
#define NTHREADS 256

typedef unsigned long long ull;

// smem float-offset layout
#define OFF_Q0    0                   // q0 packed: ull q0p[10][2048] = 40960 floats
#define OFF_VA    40960               // v buffer A (4356)
#define OFF_VB    (OFF_VA + VSZ)      // 45316
#define OFF_SW2   (OFF_VB + VSZ)      // 49672 (90 x float2 dup weights) — 8B aligned
#define OFF_SWQ   (OFF_SW2 + 180)     // 49852 (Wq scalar, 90)
#define OFF_WEFF  (OFF_SWQ + 90)      // 49942 (18)
#define OFF_BEFF  (OFF_WEFF + 18)     // 49960 (1)
#define OFF_RED   (OFF_BEFF + 1)      // 49961 (8)
#define SMEM_FLOATS (OFF_RED + 8)     // 49969
#define SMEM_BYTES  (SMEM_FLOATS * 4) // ~195.2 KB

__device__ __forceinline__ ull pk(float lo, float hi) {
    ull r; asm("mov.b64 %0, {%1, %2};" : "=l"(r) : "f"(lo), "f"(hi)); return r;
}
__device__ __forceinline__ void upk(ull p, float& lo, float& hi) {
    asm("mov.b64 {%0, %1}, %2;" : "=f"(lo), "=f"(hi) : "l"(p));
}
__device__ __forceinline__ ull fma2(ull a, ull b, ull c) {
    ull d; asm("fma.rn.f32x2 %0, %1, %2, %3;" : "=l"(d) : "l"(a), "l"(b), "l"(c)); return d;
}

// One value-iteration step on a pixel-pair x (x0, x0+1), 8 rows, packed f32x2.
// q_c = q0_c + conv3x3(v, w_c); v' = max_c q_c. If LAST, writes q to gmem.
template<bool LAST>
__device__ __forceinline__ void iter_body(
    const float* __restrict__ vcur, float* __restrict__ vnxt,
    const ull* __restrict__ q0p, const ull* __restrict__ sw2,
    int y0, int x0, int px, float* __restrict__ qout_b,
    float vlo[8], float vhi[8])
{
    // build shifted packed windows for 10 buffer rows (y0 .. y0+9)
    ull s[10][3];
#pragma unroll
    for (int r = 0; r < 10; r++) {
        const float* row = vcur + (y0 + r) * VW + x0;   // 8B aligned (x0 even)
        ull p01 = *(const ull*)(row);
        ull p23 = *(const ull*)(row + 2);
        float v0, v1, v2, v3;
        upk(p01, v0, v1); upk(p23, v2, v3);
        s[r][0] = p01;
        s[r][1] = pk(v1, v2);
        s[r][2] = p23;
    }
#pragma unroll
    for (int r = 0; r < 8; r++) { vlo[r] = -CUDART_INF_F; vhi[r] = -CUDART_INF_F; }

#pragma unroll
    for (int c = 0; c < LQ; c++) {
        ull wp[9];
#pragma unroll
        for (int t = 0; t < 9; t++) wp[t] = sw2[c * 9 + t];   // broadcast LDS.64
#pragma unroll
        for (int r = 0; r < 8; r++) {
            ull acc = q0p[c * 2048 + (y0 + r) * 32 + px];     // conflict-free LDS.64
            acc = fma2(wp[0], s[r    ][0], acc);
            acc = fma2(wp[1], s[r    ][1], acc);
            acc = fma2(wp[2], s[r    ][2], acc);
            acc = fma2(wp[3], s[r + 1][0], acc);
            acc = fma2(wp[4], s[r + 1][1], acc);
            acc = fma2(wp[5], s[r + 1][2], acc);
            acc = fma2(wp[6], s[r + 2][0], acc);
            acc = fma2(wp[7], s[r + 2][1], acc);
            acc = fma2(wp[8], s[r + 2][2], acc);
            float alo, ahi; upk(acc, alo, ahi);
            vlo[r] = fmaxf(vlo[r], alo);
            vhi[r] = fmaxf(vhi[r], ahi);
            if (LAST)
                *(ull*)(qout_b + (size_t)c * HW + (y0 + r) * WWID + x0) = acc;
        }
    }
#pragma unroll
    for (int r = 0; r < 8; r++) {
        vnxt[(y0 + r + 1) * VW + x0 + 1] = vlo[r];
        vnxt[(y0 + r + 1) * VW + x0 + 2] = vhi[r];
    }
}

__global__ void __launch_bounds__(NTHREADS, 1)
vin_kernel(const float* __restrict__ X,  const float* __restrict__ Wh,
           const float* __restrict__ bh, const float* __restrict__ Wr,
           const float* __restrict__ Wq, const float* __restrict__ w,
           const float* __restrict__ Wc, const float* __restrict__ bc,
           float* __restrict__ out)
{
    extern __shared__ float smem[];
    ull*   q0p   = (ull*)(smem + OFF_Q0);
    float* vbufA = smem + OFF_VA;
    float* vbufB = smem + OFF_VB;
    ull*   sw2   = (ull*)(smem + OFF_SW2);
    float* sWq   = smem + OFF_SWQ;
    float* sweff = smem + OFF_WEFF;
    float* sbeff = smem + OFF_BEFF;
    float* sred  = smem + OFF_RED;

    const int tid = threadIdx.x;
    const int b   = blockIdx.x;
    const int px  = tid & 31;      // pixel-pair index within a row
    const int x0  = px << 1;       // left column of the pair
    const int ty  = tid >> 5;      // 8 row-strips
    const int y0  = ty << 3;       // 8 rows per thread

    // ---- stage 1: zero v buffers (halo stays 0), stage weights, Weff partials ----
    for (int i = tid; i < VSZ; i += NTHREADS) { vbufA[i] = 0.f; vbufB[i] = 0.f; }
    if (tid < 90) {
        const float wv = w[tid];
        sw2[tid] = pk(wv, wv);
        sWq[tid] = Wq[tid];
    }
    {
        const int g = ty, k = px;   // 8 groups x 32 lanes
        float* scratch = smem + OFF_Q0;
        if (k < 19) {
            float s = 0.f;
            for (int lh = g; lh < LH; lh += 8) {
                const float wr = Wr[lh];
                s += wr * ((k < 18) ? Wh[lh * 18 + k] : bh[lh]);
            }
            scratch[g * 19 + k] = s;
        }
    }
    __syncthreads();

    // ---- stage 2: finalize Weff/beff; load X (2 channels) into v buffers ----
    if (tid < 19) {
        const float* scratch = smem + OFF_Q0;
        float s = 0.f;
#pragma unroll
        for (int g = 0; g < 8; g++) s += scratch[g * 19 + tid];
        if (tid < 18) sweff[tid] = s; else sbeff[0] = s;
    }
    const float* Xb = X + (size_t)b * 2 * HW;
    for (int i = tid; i < HW; i += NTHREADS) {
        const int yy = i >> 6, xx = i & 63;
        vbufA[(yy + 1) * VW + xx + 1] = Xb[i];
        vbufB[(yy + 1) * VW + xx + 1] = Xb[HW + i];
    }
    __syncthreads();

    // ---- stage 3: r = conv3x3(X, Weff) + beff (registers) ----
    float rr[8][2];
    {
        float wef[18];
#pragma unroll
        for (int i = 0; i < 18; i++) wef[i] = sweff[i];
        const float be = sbeff[0];
        float va[10][4], vb[10][4];
#pragma unroll
        for (int r = 0; r < 10; r++)
#pragma unroll
            for (int d = 0; d < 4; d++) {
                va[r][d] = vbufA[(y0 + r) * VW + x0 + d];
                vb[r][d] = vbufB[(y0 + r) * VW + x0 + d];
            }
#pragma unroll
        for (int r = 0; r < 8; r++)
#pragma unroll
            for (int d = 0; d < 2; d++) {
                float acc = be;
#pragma unroll
                for (int t = 0; t < 9; t++) {
                    const int ky = t / 3, kx = t % 3;
                    acc = fmaf(wef[t],     va[r + ky][d + kx], acc);
                    acc = fmaf(wef[9 + t], vb[r + ky][d + kx], acc);
                }
                rr[r][d] = acc;
            }
    }
    __syncthreads();   // all X reads done before overwriting vbufA with r
#pragma unroll
    for (int r = 0; r < 8; r++) {
        vbufA[(y0 + r + 1) * VW + x0 + 1] = rr[r][0];
        vbufA[(y0 + r + 1) * VW + x0 + 2] = rr[r][1];
    }
    __syncthreads();

    // ---- stage 4: q0 = conv3x3(r, Wq) into packed smem; v0 = max_c q0 ----
    {
        float vr[10][4];
#pragma unroll
        for (int r = 0; r < 10; r++)
#pragma unroll
            for (int d = 0; d < 4; d++)
                vr[r][d] = vbufA[(y0 + r) * VW + x0 + d];
        float vm0[8], vm1[8];
#pragma unroll
        for (int r = 0; r < 8; r++) { vm0[r] = -CUDART_INF_F; vm1[r] = -CUDART_INF_F; }
#pragma unroll
        for (int c = 0; c < LQ; c++) {
            float wq[9];
#pragma unroll
            for (int t = 0; t < 9; t++) wq[t] = sWq[c * 9 + t];
#pragma unroll
            for (int r = 0; r < 8; r++) {
                float a0 = 0.f, a1 = 0.f;
#pragma unroll
                for (int t = 0; t < 9; t++) {
                    const int ky = t / 3, kx = t % 3;
                    a0 = fmaf(wq[t], vr[r + ky][kx],     a0);
                    a1 = fmaf(wq[t], vr[r + ky][kx + 1], a1);
                }
                q0p[c * 2048 + (y0 + r) * 32 + px] = pk(a0, a1);
                vm0[r] = fmaxf(vm0[r], a0);
                vm1[r] = fmaxf(vm1[r], a1);
            }
        }
#pragma unroll
        for (int r = 0; r < 8; r++) {
            vbufB[(y0 + r + 1) * VW + x0 + 1] = vm0[r];
            vbufB[(y0 + r + 1) * VW + x0 + 2] = vm1[r];
        }
    }

    // ---- stage 5: K=40 value-iteration steps, packed math, all in smem ----
    float* out_critic = out;
    float* out_q      = out + NB;
    float* qout_b     = out_q + (size_t)b * LQ * HW;
    float vlo[8], vhi[8];
    float* vcur = vbufB;
    float* vnxt = vbufA;
#pragma unroll 1
    for (int k = 0; k < KITER - 1; k++) {
        __syncthreads();
        iter_body<false>(vcur, vnxt, q0p, sw2, y0, x0, px, qout_b, vlo, vhi);
        float* t = vcur; vcur = vnxt; vnxt = t;
    }
    __syncthreads();
    iter_body<true>(vcur, vnxt, q0p, sw2, y0, x0, px, qout_b, vlo, vhi);

    // ---- stage 6: critic = dot(v_final, Wc) + bc ----
    float part = 0.f;
#pragma unroll
    for (int r = 0; r < 8; r++) {
        part = fmaf(vlo[r], Wc[(y0 + r) * WWID + x0],     part);
        part = fmaf(vhi[r], Wc[(y0 + r) * WWID + x0 + 1], part);
    }
#pragma unroll
    for (int off = 16; off > 0; off >>= 1)
        part += __shfl_down_sync(0xffffffffu, part, off);
    if (px == 0) sred[ty] = part;
    __syncthreads();
    if (tid < 32) {
        float s = (tid < 8) ? sred[tid] : 0.f;
#pragma unroll
        for (int off = 4; off > 0; off >>= 1)
            s += __shfl_down_sync(0xffffffffu, s, off);
        if (tid == 0) out_critic[b] = s + bc[0];
    }
}

extern "C" void kernel_launch(void* const* d_in, const int* in_sizes, int n_in,
                              void* d_out, int out_size) {
    const float* X  = (const float*)d_in[0];
    const float* Wh = (const float*)d_in[1];
    const float* bh = (const float*)d_in[2];
    const float* Wr = (const float*)d_in[3];
    const float* Wq = (const float*)d_in[4];
    const float* w  = (const float*)d_in[5];
    const float* Wc = (const float*)d_in[6];
    const float* bc = (const float*)d_in[7];
    float* out = (float*)d_out;

    cudaFuncSetAttribute(vin_kernel, cudaFuncAttributeMaxDynamicSharedMemorySize,
                         SMEM_BYTES);
    vin_kernel<<<NB, NTHREADS, SMEM_BYTES>>>(X, Wh, bh, Wr, Wq, w, Wc, bc, out);
}